// round 1
// baseline (speedup 1.0000x reference)
#include <cuda_runtime.h>

#define N_NODESC 100000
#define N_EDGESC 1600000
#define N_GRAPHSC 512
#define F_INC 64
#define HC 128
#define H3C 384
#define STEPSC 6

// ---------------- device scratch (no allocations allowed) ----------------
__device__ float g_hA[(size_t)N_NODESC * HC];
__device__ float g_hB[(size_t)N_NODESC * HC];
__device__ float g_agg[(size_t)N_NODESC * HC];
__device__ float g_Wc[STEPSC * HC * H3C];   // interleaved cols: 3*f+{r,z,n}
__device__ float g_Whh[HC * H3C];           // W_hh^T, interleaved cols
__device__ float g_bi[H3C];
__device__ float g_bh[H3C];
__device__ float g_sums[N_GRAPHSC * HC];
__device__ float g_cnt[N_GRAPHSC];
__device__ int   g_is64;

// ---------------- helpers ----------------
__device__ __forceinline__ unsigned long long pk2(float x) {
    unsigned long long r;
    asm("mov.b64 %0, {%1, %1};" : "=l"(r) : "f"(x));
    return r;
}
__device__ __forceinline__ void fma2(unsigned long long& d, unsigned long long a, unsigned long long b) {
    asm("fma.rn.f32x2 %0, %1, %2, %0;" : "+l"(d) : "l"(a), "l"(b));
}
__device__ __forceinline__ float2 upk(unsigned long long v) {
    float2 f;
    asm("mov.b64 {%0, %1}, %2;" : "=f"(f.x), "=f"(f.y) : "l"(v));
    return f;
}
__device__ __forceinline__ void red4(float* p, float4 v) {
    asm volatile("red.global.add.v4.f32 [%0], {%1,%2,%3,%4};"
                 :: "l"(p), "f"(v.x), "f"(v.y), "f"(v.z), "f"(v.w) : "memory");
}
__device__ __forceinline__ float sigmoidf(float x) { return 1.0f / (1.0f + expf(-x)); }

__device__ __forceinline__ int load_idx(const void* p, long long i, int is64) {
    if (is64) return (int)((const long long*)p)[i];
    return ((const int*)p)[i];
}

// ---------------- index dtype sniffer ----------------
// If edge_index is int64 (values < 2^31), every odd 32-bit word is 0.
__global__ void k_detect(const int* __restrict__ ei) {
    int any = 0;
    for (int i = threadIdx.x; i < 2048; i += blockDim.x)
        any |= ei[2 * i + 1];
    any = __syncthreads_or(any);
    if (threadIdx.x == 0) g_is64 = (any == 0) ? 1 : 0;
}

// ---------------- weight precompute ----------------
// Wc[s][k][3f+g] = sum_m W_mp[s][k][m] * W_ih[g*128+f][m]
__global__ void k_prep_wc(const float* __restrict__ Wmp, const float* __restrict__ Wih) {
    int idx = blockIdx.x * blockDim.x + threadIdx.x;
    if (idx >= STEPSC * HC * H3C) return;
    int jc = idx % H3C;
    int k  = (idx / H3C) % HC;
    int s  = idx / (H3C * HC);
    int f = jc / 3, g = jc % 3;
    const float4* wm = (const float4*)(Wmp + ((size_t)s * HC + k) * HC);
    const float4* wi = (const float4*)(Wih + (size_t)(g * HC + f) * HC);
    float acc = 0.f;
#pragma unroll
    for (int m = 0; m < HC / 4; m++) {
        float4 a = wm[m], b = wi[m];
        acc += a.x * b.x + a.y * b.y + a.z * b.z + a.w * b.w;
    }
    g_Wc[idx] = acc;
}

// Whh_i[k][3f+g] = W_hh[g*128+f][k] ; interleave biases
__global__ void k_prep_misc(const float* __restrict__ Whh_in,
                            const float* __restrict__ bih, const float* __restrict__ bhh) {
    int idx = blockIdx.x * blockDim.x + threadIdx.x;
    if (idx < HC * H3C) {
        int jc = idx % H3C;
        int k  = idx / H3C;
        int f = jc / 3, g = jc % 3;
        g_Whh[k * H3C + jc] = Whh_in[(size_t)(g * HC + f) * HC + k];
    }
    if (idx < H3C) {
        int f = idx / 3, g = idx % 3;
        g_bi[idx] = bih[g * HC + f];
        g_bh[idx] = bhh[g * HC + f];
    }
}

// ---------------- input layer: h = tanh(x @ W_in) ----------------
__global__ void k_input(const float* __restrict__ x, const float* __restrict__ Win,
                        float* __restrict__ h) {
    __shared__ float sw[F_INC * HC];
    __shared__ float sx[4][F_INC];
    int tid = threadIdx.x;  // 128
    for (int i = tid; i < F_INC * HC; i += 128) sw[i] = Win[i];
    int base = blockIdx.x * 64;
    for (int n0 = 0; n0 < 64; n0 += 4) {
        __syncthreads();
        for (int i = tid; i < 4 * F_INC; i += 128) {
            int ni = i / F_INC, k = i % F_INC;
            int node = base + n0 + ni;
            sx[ni][k] = (node < N_NODESC) ? x[(size_t)node * F_INC + k] : 0.f;
        }
        __syncthreads();
        float a0 = 0, a1 = 0, a2 = 0, a3 = 0;
#pragma unroll
        for (int k = 0; k < F_INC; k++) {
            float w = sw[k * HC + tid];
            a0 += sx[0][k] * w; a1 += sx[1][k] * w;
            a2 += sx[2][k] * w; a3 += sx[3][k] * w;
        }
        int node = base + n0;
        if (node + 0 < N_NODESC) h[(size_t)(node + 0) * HC + tid] = tanhf(a0);
        if (node + 1 < N_NODESC) h[(size_t)(node + 1) * HC + tid] = tanhf(a1);
        if (node + 2 < N_NODESC) h[(size_t)(node + 2) * HC + tid] = tanhf(a2);
        if (node + 3 < N_NODESC) h[(size_t)(node + 3) * HC + tid] = tanhf(a3);
    }
}

// ---------------- edge scatter: agg[dst] += h[src] (warp per edge) ----------------
__global__ void k_scatter(const void* __restrict__ ei, const float* __restrict__ h) {
    int w = (blockIdx.x * blockDim.x + threadIdx.x) >> 5;
    int lane = threadIdx.x & 31;
    if (w >= N_EDGESC) return;
    int is64 = g_is64;
    int s = load_idx(ei, w, is64);
    int d = load_idx(ei, (long long)N_EDGESC + w, is64);
    float4 v = *((const float4*)(h + (size_t)s * HC) + lane);
    float* p = (float*)((float4*)(g_agg + (size_t)d * HC) + lane);
    red4(p, v);
}

// ---------------- fused dual-GEMM + GRU ----------------
// gi = agg @ Wc[s] + b_i ; gh = h @ Whh^T + b_h ; GRU gates -> hout
#define BM 64
#define BN 96
#define BK 32

__global__ __launch_bounds__(256) void k_gru(const float* __restrict__ hin,
                                             float* __restrict__ hout,
                                             const float* __restrict__ Wc) {
    __shared__ __align__(16) float sA1[BK][68];  // agg, k-major
    __shared__ __align__(16) float sA2[BK][68];  // h,   k-major
    __shared__ __align__(16) float sB1[BK][BN];
    __shared__ __align__(16) float sB2[BK][BN];

    int tid = threadIdx.x;
    int tx = tid & 15, ty = tid >> 4;
    int row0 = blockIdx.x * BM;
    int ct = blockIdx.y * BN;
    int c0 = tx * 6;

    unsigned long long acc1[4][3], acc2[4][3];
#pragma unroll
    for (int i = 0; i < 4; i++)
#pragma unroll
        for (int j = 0; j < 3; j++) { acc1[i][j] = 0ULL; acc2[i][j] = 0ULL; }

    for (int kt = 0; kt < HC; kt += BK) {
        // load A tiles (64 rows x 32 k), transposed into smem
#pragma unroll
        for (int rep = 0; rep < 2; rep++) {
            int idx = tid + rep * 256;
            int r = idx >> 3;
            int kq = idx & 7;
            int grow = row0 + r;
            float4 v1, v2;
            if (grow < N_NODESC) {
                v1 = *(const float4*)(g_agg + (size_t)grow * HC + kt + kq * 4);
                v2 = *(const float4*)(hin   + (size_t)grow * HC + kt + kq * 4);
            } else {
                v1 = make_float4(0.f, 0.f, 0.f, 0.f);
                v2 = v1;
            }
            int kk = kq * 4;
            sA1[kk + 0][r] = v1.x; sA1[kk + 1][r] = v1.y; sA1[kk + 2][r] = v1.z; sA1[kk + 3][r] = v1.w;
            sA2[kk + 0][r] = v2.x; sA2[kk + 1][r] = v2.y; sA2[kk + 2][r] = v2.z; sA2[kk + 3][r] = v2.w;
        }
        // load B tiles (32 k x 96 cols)
#pragma unroll
        for (int rep = 0; rep < 3; rep++) {
            int idx = tid + rep * 256;
            int kr = idx / 24;
            int cq = idx % 24;
            float4 v1 = *(const float4*)(Wc    + (size_t)(kt + kr) * H3C + ct + cq * 4);
            float4 v2 = *(const float4*)(g_Whh + (size_t)(kt + kr) * H3C + ct + cq * 4);
            *(float4*)&sB1[kr][cq * 4] = v1;
            *(float4*)&sB2[kr][cq * 4] = v2;
        }
        __syncthreads();
#pragma unroll
        for (int k = 0; k < BK; k++) {
            float4 a1 = *(const float4*)&sA1[k][ty << 2];
            float4 a2 = *(const float4*)&sA2[k][ty << 2];
            unsigned long long b1[3], b2[3];
#pragma unroll
            for (int j = 0; j < 3; j++) {
                b1[j] = *(const unsigned long long*)&sB1[k][c0 + 2 * j];
                b2[j] = *(const unsigned long long*)&sB2[k][c0 + 2 * j];
            }
            float av1[4] = {a1.x, a1.y, a1.z, a1.w};
            float av2[4] = {a2.x, a2.y, a2.z, a2.w};
#pragma unroll
            for (int i = 0; i < 4; i++) {
                unsigned long long aa1 = pk2(av1[i]);
                unsigned long long aa2 = pk2(av2[i]);
#pragma unroll
                for (int j = 0; j < 3; j++) {
                    fma2(acc1[i][j], aa1, b1[j]);
                    fma2(acc2[i][j], aa2, b2[j]);
                }
            }
        }
        __syncthreads();
    }

    const float* bi = g_bi + ct;
    const float* bh = g_bh + ct;
    int f0 = (ct + c0) / 3;  // two consecutive features per thread
#pragma unroll
    for (int i = 0; i < 4; i++) {
        int row = row0 + (ty << 2) + i;
        if (row < N_NODESC) {
            float2 p10 = upk(acc1[i][0]), p11 = upk(acc1[i][1]), p12 = upk(acc1[i][2]);
            float2 p20 = upk(acc2[i][0]), p21 = upk(acc2[i][1]), p22 = upk(acc2[i][2]);
            // feature 0: (r,z,n) = cols c0+0..2 ; feature 1: cols c0+3..5
            float gi_r0 = p10.x + bi[c0 + 0], gi_z0 = p10.y + bi[c0 + 1], gi_n0 = p11.x + bi[c0 + 2];
            float gh_r0 = p20.x + bh[c0 + 0], gh_z0 = p20.y + bh[c0 + 1], gh_n0 = p21.x + bh[c0 + 2];
            float gi_r1 = p11.y + bi[c0 + 3], gi_z1 = p12.x + bi[c0 + 4], gi_n1 = p12.y + bi[c0 + 5];
            float gh_r1 = p21.y + bh[c0 + 3], gh_z1 = p22.x + bh[c0 + 4], gh_n1 = p22.y + bh[c0 + 5];
            float h0 = hin[(size_t)row * HC + f0];
            float h1 = hin[(size_t)row * HC + f0 + 1];
            float r0 = sigmoidf(gi_r0 + gh_r0);
            float z0 = sigmoidf(gi_z0 + gh_z0);
            float n0 = tanhf(gi_n0 + r0 * gh_n0);
            float r1 = sigmoidf(gi_r1 + gh_r1);
            float z1 = sigmoidf(gi_z1 + gh_z1);
            float n1 = tanhf(gi_n1 + r1 * gh_n1);
            hout[(size_t)row * HC + f0]     = (1.f - z0) * n0 + z0 * h0;
            hout[(size_t)row * HC + f0 + 1] = (1.f - z1) * n1 + z1 * h1;
        }
    }
}

// ---------------- pooling ----------------
__global__ void k_pool(const float* __restrict__ h, const void* __restrict__ batch) {
    int w = (blockIdx.x * blockDim.x + threadIdx.x) >> 5;
    int lane = threadIdx.x & 31;
    if (w >= N_NODESC) return;
    int g = load_idx(batch, w, g_is64);
    float4 v = *((const float4*)(h + (size_t)w * HC) + lane);
    float* p = (float*)((float4*)(g_sums + (size_t)g * HC) + lane);
    red4(p, v);
    if (lane == 0) atomicAdd(&g_cnt[g], 1.0f);
}

__global__ void k_out(const float* __restrict__ Wp, const float* __restrict__ bp,
                      float* __restrict__ out) {
    int g = blockIdx.x;
    int t = threadIdx.x;  // 128
    float c = fmaxf(g_cnt[g], 1.0f);
    float pooled = g_sums[g * HC + t] / c;
    float v = fmaxf(pooled, 0.f) * Wp[t];
    __shared__ float red[4];
#pragma unroll
    for (int o = 16; o > 0; o >>= 1) v += __shfl_down_sync(0xffffffff, v, o);
    if ((t & 31) == 0) red[t >> 5] = v;
    __syncthreads();
    if (t == 0) out[g] = red[0] + red[1] + red[2] + red[3] + bp[0];
}

// ---------------- launch ----------------
extern "C" void kernel_launch(void* const* d_in, const int* in_sizes, int n_in,
                              void* d_out, int out_size) {
    const float* x    = (const float*)d_in[0];
    const void*  ei   = d_in[1];
    const void*  batch= d_in[2];
    const float* W_in = (const float*)d_in[3];
    const float* W_mp = (const float*)d_in[4];
    const float* W_ih = (const float*)d_in[5];
    const float* W_hh = (const float*)d_in[6];
    const float* b_ih = (const float*)d_in[7];
    const float* b_hh = (const float*)d_in[8];
    const float* W_p  = (const float*)d_in[9];
    const float* b_p  = (const float*)d_in[10];
    float* out = (float*)d_out;

    void *aggPtr, *hA, *hB, *sumsPtr, *cntPtr, *wcPtr;
    cudaGetSymbolAddress(&aggPtr, g_agg);
    cudaGetSymbolAddress(&hA, g_hA);
    cudaGetSymbolAddress(&hB, g_hB);
    cudaGetSymbolAddress(&sumsPtr, g_sums);
    cudaGetSymbolAddress(&cntPtr, g_cnt);
    cudaGetSymbolAddress(&wcPtr, g_Wc);

    k_detect<<<1, 256>>>((const int*)ei);
    k_prep_wc<<<(STEPSC * HC * H3C + 255) / 256, 256>>>(W_mp, W_ih);
    k_prep_misc<<<(HC * H3C + 255) / 256, 256>>>(W_hh, b_ih, b_hh);
    k_input<<<(N_NODESC + 63) / 64, 128>>>(x, W_in, (float*)hA);

    float* hcur = (float*)hA;
    float* hnext = (float*)hB;
    for (int s = 0; s < STEPSC; s++) {
        cudaMemsetAsync(aggPtr, 0, (size_t)N_NODESC * HC * sizeof(float), 0);
        k_scatter<<<(int)(((long long)N_EDGESC * 32 + 255) / 256), 256>>>(ei, hcur);
        dim3 grid((N_NODESC + BM - 1) / BM, H3C / BN);
        k_gru<<<grid, 256>>>(hcur, hnext, (const float*)wcPtr + (size_t)s * HC * H3C);
        float* tmp = hcur; hcur = hnext; hnext = tmp;
    }
    cudaMemsetAsync(sumsPtr, 0, (size_t)N_GRAPHSC * HC * sizeof(float), 0);
    cudaMemsetAsync(cntPtr, 0, (size_t)N_GRAPHSC * sizeof(float), 0);
    k_pool<<<(int)(((long long)N_NODESC * 32 + 255) / 256), 256>>>(hcur, batch);
    k_out<<<N_GRAPHSC, 128>>>(W_p, b_p, out);
}

// round 5
// speedup vs baseline: 1.0024x; 1.0024x over previous
#include <cuda_runtime.h>
#include <cstdint>

#define N_NODESC 100000
#define N_EDGESC 1600000
#define N_GRAPHSC 512
#define F_INC 64
#define HC 128
#define H3C 384
#define STEPSC 6
#define NTILES ((N_NODESC + 127) / 128)
#define IMG_TILE 2080                    // floats per 16x128 weight tile image (4 blocks * 520)
#define IMG_STEP (4 * 16 * IMG_TILE)     // floats per step (4 col strips x 16 k tiles)
#define IMG_ELEMS_PER_STEP (4 * 16 * 2048)   // logical elements per step = 131072
#define BUF_STRIDE (4 * IMG_TILE)        // Ahi|Alo|Bhi|Blo per buffer
#define SMEM_DYN (2 * BUF_STRIDE * 4)    // bytes: 66560

// ---------------- device scratch ----------------
__device__ float g_hA[(size_t)N_NODESC * HC];
__device__ float g_hB[(size_t)N_NODESC * HC];
__device__ float g_agg[(size_t)N_NODESC * HC];
__device__ float g_WcG[(size_t)STEPSC * H3C * HC];     // grouped (r|z|n): [s][gate*128+f][k]
__device__ float g_WimgHi[(size_t)STEPSC * IMG_STEP];  // tf32 hi image
__device__ float g_WimgLo[(size_t)STEPSC * IMG_STEP];  // tf32 lo image
__device__ float g_sums[N_GRAPHSC * HC];
__device__ float g_cnt[N_GRAPHSC];
__device__ int   g_is64;

// ---------------- helpers ----------------
__device__ __forceinline__ uint32_t smem_u32(const void* p) {
    uint32_t a;
    asm("{ .reg .u64 t; cvta.to.shared.u64 t, %1; cvt.u32.u64 %0, t; }" : "=r"(a) : "l"(p));
    return a;
}
__device__ __forceinline__ uint32_t cvt_tf32(float x) {
    uint32_t r;
    asm("cvt.rna.tf32.f32 %0, %1;" : "=r"(r) : "f"(x));
    return r;
}
__device__ __forceinline__ void red4(float* p, float4 v) {
    asm volatile("red.global.add.v4.f32 [%0], {%1,%2,%3,%4};"
                 :: "l"(p), "f"(v.x), "f"(v.y), "f"(v.z), "f"(v.w) : "memory");
}
__device__ __forceinline__ int load_idx(const void* p, long long i, int is64) {
    if (is64) return (int)((const long long*)p)[i];
    return ((const int*)p)[i];
}
__device__ __forceinline__ float sigf(float x) {
    return __fdividef(1.0f, 1.0f + __expf(-x));
}
__device__ __forceinline__ float tanhfast(float x) {
    float e = __expf(2.0f * x);
    return 1.0f - __fdividef(2.0f, e + 1.0f);
}
__device__ __forceinline__ void mma_tf32(float* d, uint32_t a0, uint32_t a1, uint32_t a2,
                                         uint32_t a3, uint32_t b0, uint32_t b1) {
    asm volatile(
        "mma.sync.aligned.m16n8k8.row.col.f32.tf32.tf32.f32 "
        "{%0,%1,%2,%3}, {%4,%5,%6,%7}, {%8,%9}, {%0,%1,%2,%3};"
        : "+f"(d[0]), "+f"(d[1]), "+f"(d[2]), "+f"(d[3])
        : "r"(a0), "r"(a1), "r"(a2), "r"(a3), "r"(b0), "r"(b1));
}
__device__ __forceinline__ void cpasync16(uint32_t saddr, const void* g) {
    asm volatile("cp.async.cg.shared.global [%0], [%1], 16;" :: "r"(saddr), "l"(g) : "memory");
}
__device__ __forceinline__ void cp_commit() {
    asm volatile("cp.async.commit_group;" ::: "memory");
}
__device__ __forceinline__ void cp_wait1() {
    asm volatile("cp.async.wait_group 1;" ::: "memory");
}
__device__ __forceinline__ void cp_wait0() {
    asm volatile("cp.async.wait_group 0;" ::: "memory");
}

// ---------------- index dtype sniffer ----------------
__global__ void k_detect(const int* __restrict__ ei) {
    int any = 0;
    for (int i = threadIdx.x; i < 2048; i += blockDim.x) any |= ei[2 * i + 1];
    any = __syncthreads_or(any);
    if (threadIdx.x == 0) g_is64 = (any == 0) ? 1 : 0;
}

// ---------------- weight precompute ----------------
// WcG[s][gate*128+f][k] = sum_m Wmp[s][k][m] * Wih[gate*128+f][m]
__global__ void k_prep_wc(const float* __restrict__ Wmp, const float* __restrict__ Wih) {
    int idx = blockIdx.x * blockDim.x + threadIdx.x;
    if (idx >= STEPSC * H3C * HC) return;
    int k = idx % HC;
    int j = (idx / HC) % H3C;
    int s = idx / (HC * H3C);
    const float4* wm = (const float4*)(Wmp + ((size_t)s * HC + k) * HC);
    const float4* wi = (const float4*)(Wih + (size_t)j * HC);
    float acc = 0.f;
#pragma unroll
    for (int m = 0; m < HC / 4; m++) {
        float4 a = wm[m], b = wi[m];
        acc += a.x * b.x + a.y * b.y + a.z * b.z + a.w * b.w;
    }
    g_WcG[idx] = acc;
}

// Build padded/blocked smem images (hi + lo tf32 split) of Wbig[256][512].
// Column layout: col = 4*f_local + gate, gate in {0:r, 1:z, 2:n, 3:hn}.
// Rows k<128: agg part (WcG, hn col = 0). Rows k>=128: h part (Whh; hn col = Whh_n).
__global__ void k_prep_img(const float* __restrict__ Whh) {
    int idx = blockIdx.x * blockDim.x + threadIdx.x;
    if (idx >= STEPSC * IMG_ELEMS_PER_STEP) return;
    int j  = idx & 3;
    int cl = (idx >> 2) & 127;
    int b  = (idx >> 9) & 3;
    int kt = (idx >> 11) & 15;
    int ys = (idx >> 15) & 3;
    int s  = idx >> 17;
    int k = kt * 16 + b * 4 + j;
    int colg = ys * 128 + cl;
    int f = colg >> 2;
    int gate = colg & 3;
    float val;
    if (k < HC) {
        val = (gate < 3) ? g_WcG[((size_t)s * H3C + gate * HC + f) * HC + k] : 0.f;
    } else {
        int g2 = (gate == 3) ? 2 : gate;
        val = Whh[(size_t)(g2 * HC + f) * HC + (k - HC)];
    }
    float vhi = __uint_as_float(cvt_tf32(val));
    float vlo = __uint_as_float(cvt_tf32(val - vhi));
    size_t off = ((size_t)(s * 4 + ys) * 16 + kt) * IMG_TILE + b * 520 + cl * 4 + j;
    g_WimgHi[off] = vhi;
    g_WimgLo[off] = vlo;
}

// ---------------- input layer: h = tanh(x @ W_in) ----------------
__global__ void k_input(const float* __restrict__ x, const float* __restrict__ Win,
                        float* __restrict__ h) {
    __shared__ float sw[F_INC * HC];
    __shared__ float sx[4][F_INC];
    int tid = threadIdx.x;  // 128
    for (int i = tid; i < F_INC * HC; i += 128) sw[i] = Win[i];
    int base = blockIdx.x * 64;
    for (int n0 = 0; n0 < 64; n0 += 4) {
        __syncthreads();
        for (int i = tid; i < 4 * F_INC; i += 128) {
            int ni = i / F_INC, k = i % F_INC;
            int node = base + n0 + ni;
            sx[ni][k] = (node < N_NODESC) ? x[(size_t)node * F_INC + k] : 0.f;
        }
        __syncthreads();
        float a0 = 0, a1 = 0, a2 = 0, a3 = 0;
#pragma unroll
        for (int k = 0; k < F_INC; k++) {
            float w = sw[k * HC + tid];
            a0 += sx[0][k] * w; a1 += sx[1][k] * w;
            a2 += sx[2][k] * w; a3 += sx[3][k] * w;
        }
        int node = base + n0;
        if (node + 0 < N_NODESC) h[(size_t)(node + 0) * HC + tid] = tanhf(a0);
        if (node + 1 < N_NODESC) h[(size_t)(node + 1) * HC + tid] = tanhf(a1);
        if (node + 2 < N_NODESC) h[(size_t)(node + 2) * HC + tid] = tanhf(a2);
        if (node + 3 < N_NODESC) h[(size_t)(node + 3) * HC + tid] = tanhf(a3);
    }
}

// ---------------- edge scatter: agg[dst] += h[src] ----------------
__global__ void k_scatter(const void* __restrict__ ei, const float* __restrict__ h) {
    int w = (blockIdx.x * blockDim.x + threadIdx.x) >> 5;
    int lane = threadIdx.x & 31;
    if (w >= N_EDGESC) return;
    int is64 = g_is64;
    int s = load_idx(ei, w, is64);
    int d = load_idx(ei, (long long)N_EDGESC + w, is64);
    float4 v = *((const float4*)(h + (size_t)s * HC) + lane);
    float* p = (float*)((float4*)(g_agg + (size_t)d * HC) + lane);
    red4(p, v);
}

// ---------------- 3xTF32 mma.sync fused GEMM + GRU ----------------
// CTA tile: 128 rows x 128 cols (= 32 features x 4 gates). K = 256 ([agg|h]).
// acc = Ahi*Bhi + Ahi*Blo + Alo*Bhi  (3xTF32, ~fp32 accuracy)
__global__ void __launch_bounds__(256) k_gemm(
    const float* __restrict__ hin, float* __restrict__ hout,
    const float* __restrict__ WimgHi, const float* __restrict__ WimgLo,
    const float* __restrict__ bih, const float* __restrict__ bhh)
{
    extern __shared__ float sm[];  // [2][Ahi|Alo|Bhi|Blo], each IMG_TILE floats
    __shared__ float sbias[4][32];

    const int tid = threadIdx.x;
    const int lane = tid & 31;
    const int warp = tid >> 5;
    const int warpM = warp & 1;
    const int warpN = warp >> 1;
    const int g = lane >> 2;
    const int tI = lane & 3;
    const int row0 = blockIdx.x * 128;
    const int ys = blockIdx.y;

    if (tid < 32) {
        int f = ys * 32 + tid;
        sbias[0][tid] = bih[f] + bhh[f];
        sbias[1][tid] = bih[HC + f] + bhh[HC + f];
        sbias[2][tid] = bih[2 * HC + f];
        sbias[3][tid] = bhh[2 * HC + f];
    }

    const float* WHi = WimgHi + (size_t)ys * 16 * IMG_TILE;
    const float* WLo = WimgLo + (size_t)ys * 16 * IMG_TILE;

    float acc[4][4][4];
#pragma unroll
    for (int mt = 0; mt < 4; mt++)
#pragma unroll
        for (int nt = 0; nt < 4; nt++)
#pragma unroll
            for (int r = 0; r < 4; r++) acc[mt][nt][r] = 0.f;

    // ---- B tile async copy: 520 hi-chunks + 520 lo-chunks of 16B ----
    auto issueB = [&](int kt) {
        uint32_t bB = smem_u32(sm) + ((kt & 1) * BUF_STRIDE + 2 * IMG_TILE) * 4;
        const float4* hi4 = (const float4*)(WHi + (size_t)kt * IMG_TILE);
        const float4* lo4 = (const float4*)(WLo + (size_t)kt * IMG_TILE);
#pragma unroll
        for (int rep = 0; rep < 4; rep++) {
            int idx = tid + rep * 256;
            const float4* src = (idx < 520) ? (hi4 + idx) : (lo4 + (idx - 520));
            cpasync16(bB + idx * 16, src);
        }
        if (tid < 16) {
            int idx = 1024 + tid;
            cpasync16(bB + idx * 16, lo4 + (idx - 520));
        }
        cp_commit();
    };

    float4 av[2];
    auto loadA = [&](int kt) {
        const float* Asrc = (kt < 8) ? g_agg : hin;
        int colb = (kt & 7) * 16;
#pragma unroll
        for (int rep = 0; rep < 2; rep++) {
            int idx = tid + rep * 256;
            int row = idx >> 2, kq = idx & 3;
            int grow = row0 + row;
            av[rep] = (grow < N_NODESC)
                ? *(const float4*)(Asrc + (size_t)grow * HC + colb + kq * 4)
                : make_float4(0.f, 0.f, 0.f, 0.f);
        }
    };

    issueB(0);
    loadA(0);

    for (int kt = 0; kt < 16; kt++) {
        float* buf = sm + (kt & 1) * BUF_STRIDE;
        float* bufAhi = buf;
        float* bufAlo = buf + IMG_TILE;
        float* bufBhi = buf + 2 * IMG_TILE;
        float* bufBlo = buf + 3 * IMG_TILE;

        // STS A split (hi/lo)
#pragma unroll
        for (int rep = 0; rep < 2; rep++) {
            int idx = tid + rep * 256;
            int row = idx >> 2, kq = idx & 3;
            float4 v = av[rep];
            float4 vh, vl;
            vh.x = __uint_as_float(cvt_tf32(v.x)); vl.x = __uint_as_float(cvt_tf32(v.x - vh.x));
            vh.y = __uint_as_float(cvt_tf32(v.y)); vl.y = __uint_as_float(cvt_tf32(v.y - vh.y));
            vh.z = __uint_as_float(cvt_tf32(v.z)); vl.z = __uint_as_float(cvt_tf32(v.z - vh.z));
            vh.w = __uint_as_float(cvt_tf32(v.w)); vl.w = __uint_as_float(cvt_tf32(v.w - vh.w));
            *(float4*)(bufAhi + kq * 520 + row * 4) = vh;
            *(float4*)(bufAlo + kq * 520 + row * 4) = vl;
        }

        if (kt < 15) { issueB(kt + 1); cp_wait1(); }
        else cp_wait0();
        __syncthreads();

        if (kt < 15) loadA(kt + 1);

        // compute: 2 k8 steps, 3 MMA terms each
#pragma unroll
        for (int s8 = 0; s8 < 2; s8++) {
            int kb = 2 * s8 * 520;
            uint32_t bh[4][2], bl[4][2];
#pragma unroll
            for (int nt = 0; nt < 4; nt++) {
                int boff = kb + (warpN * 32 + nt * 8 + g) * 4 + tI;
                bh[nt][0] = __float_as_uint(bufBhi[boff]);
                bh[nt][1] = __float_as_uint(bufBhi[boff + 520]);
                bl[nt][0] = __float_as_uint(bufBlo[boff]);
                bl[nt][1] = __float_as_uint(bufBlo[boff + 520]);
            }
#pragma unroll
            for (int mt = 0; mt < 4; mt++) {
                int aoff = kb + (warpM * 64 + mt * 16 + g) * 4 + tI;
                uint32_t ah0 = __float_as_uint(bufAhi[aoff]);
                uint32_t ah1 = __float_as_uint(bufAhi[aoff + 32]);
                uint32_t ah2 = __float_as_uint(bufAhi[aoff + 520]);
                uint32_t ah3 = __float_as_uint(bufAhi[aoff + 520 + 32]);
                uint32_t al0 = __float_as_uint(bufAlo[aoff]);
                uint32_t al1 = __float_as_uint(bufAlo[aoff + 32]);
                uint32_t al2 = __float_as_uint(bufAlo[aoff + 520]);
                uint32_t al3 = __float_as_uint(bufAlo[aoff + 520 + 32]);
#pragma unroll
                for (int nt = 0; nt < 4; nt++) {
                    mma_tf32(acc[mt][nt], ah0, ah1, ah2, ah3, bh[nt][0], bh[nt][1]);
                    mma_tf32(acc[mt][nt], ah0, ah1, ah2, ah3, bl[nt][0], bl[nt][1]);
                    mma_tf32(acc[mt][nt], al0, al1, al2, al3, bh[nt][0], bh[nt][1]);
                }
            }
        }
        __syncthreads();
    }

    // ---------------- fused GRU epilogue ----------------
    float* sOut = sm;  // [128][36], aliases pipeline smem (synced above)
    const int odd = tI & 1;
    const int fl = warpN * 8 + (tI >> 1);

#pragma unroll
    for (int mt = 0; mt < 4; mt++) {
#pragma unroll
        for (int nt = 0; nt < 4; nt++) {
            float c0 = acc[mt][nt][0], c1 = acc[mt][nt][1];
            float c2 = acc[mt][nt][2], c3 = acc[mt][nt][3];
            float x0 = __shfl_xor_sync(0xffffffffu, c0, 1);
            float x1 = __shfl_xor_sync(0xffffffffu, c1, 1);
            float x2 = __shfl_xor_sync(0xffffffffu, c2, 1);
            float x3 = __shfl_xor_sync(0xffffffffu, c3, 1);
            float Sr = odd ? x2 : c0;
            float Sz = odd ? x3 : c1;
            float Sn = odd ? c2 : x0;
            float hn = odd ? c3 : x1;
            int rowl = warpM * 64 + mt * 16 + g + (odd ? 8 : 0);
            int f = fl + nt * 2;
            int grow = row0 + rowl;
            float hprev = (grow < N_NODESC) ? hin[(size_t)grow * HC + ys * 32 + f] : 0.f;
            float rr = sigf(Sr + sbias[0][f]);
            float zz = sigf(Sz + sbias[1][f]);
            float nn = tanhfast(Sn - hn + sbias[2][f] + rr * (hn + sbias[3][f]));
            sOut[rowl * 36 + f] = (1.f - zz) * nn + zz * hprev;
        }
    }
    __syncthreads();
#pragma unroll
    for (int rep = 0; rep < 4; rep++) {
        int idx = tid + rep * 256;
        int row = idx >> 3, q = idx & 7;
        int grow = row0 + row;
        if (grow < N_NODESC)
            *(float4*)(hout + (size_t)grow * HC + ys * 32 + q * 4) =
                *(const float4*)(sOut + row * 36 + q * 4);
    }
}

// ---------------- pooling ----------------
__global__ void k_pool(const float* __restrict__ h, const void* __restrict__ batch) {
    int w = (blockIdx.x * blockDim.x + threadIdx.x) >> 5;
    int lane = threadIdx.x & 31;
    if (w >= N_NODESC) return;
    int g = load_idx(batch, w, g_is64);
    float4 v = *((const float4*)(h + (size_t)w * HC) + lane);
    float* p = (float*)((float4*)(g_sums + (size_t)g * HC) + lane);
    red4(p, v);
    if (lane == 0) atomicAdd(&g_cnt[g], 1.0f);
}

__global__ void k_out(const float* __restrict__ Wp, const float* __restrict__ bp,
                      float* __restrict__ out) {
    int g = blockIdx.x;
    int t = threadIdx.x;  // 128
    float c = fmaxf(g_cnt[g], 1.0f);
    float pooled = g_sums[g * HC + t] / c;
    float v = fmaxf(pooled, 0.f) * Wp[t];
    __shared__ float red[4];
#pragma unroll
    for (int o = 16; o > 0; o >>= 1) v += __shfl_down_sync(0xffffffff, v, o);
    if ((t & 31) == 0) red[t >> 5] = v;
    __syncthreads();
    if (t == 0) out[g] = red[0] + red[1] + red[2] + red[3] + bp[0];
}

// ---------------- launch ----------------
extern "C" void kernel_launch(void* const* d_in, const int* in_sizes, int n_in,
                              void* d_out, int out_size) {
    const float* x    = (const float*)d_in[0];
    const void*  ei   = d_in[1];
    const void*  batch= d_in[2];
    const float* W_in = (const float*)d_in[3];
    const float* W_mp = (const float*)d_in[4];
    const float* W_ih = (const float*)d_in[5];
    const float* W_hh = (const float*)d_in[6];
    const float* b_ih = (const float*)d_in[7];
    const float* b_hh = (const float*)d_in[8];
    const float* W_p  = (const float*)d_in[9];
    const float* b_p  = (const float*)d_in[10];
    float* out = (float*)d_out;

    void *aggPtr, *hA, *hB, *sumsPtr, *cntPtr, *wHiPtr, *wLoPtr;
    cudaGetSymbolAddress(&aggPtr, g_agg);
    cudaGetSymbolAddress(&hA, g_hA);
    cudaGetSymbolAddress(&hB, g_hB);
    cudaGetSymbolAddress(&sumsPtr, g_sums);
    cudaGetSymbolAddress(&cntPtr, g_cnt);
    cudaGetSymbolAddress(&wHiPtr, g_WimgHi);
    cudaGetSymbolAddress(&wLoPtr, g_WimgLo);

    cudaFuncSetAttribute(k_gemm, cudaFuncAttributeMaxDynamicSharedMemorySize, SMEM_DYN);

    k_detect<<<1, 256>>>((const int*)ei);
    k_prep_wc<<<(STEPSC * H3C * HC + 255) / 256, 256>>>(W_mp, W_ih);
    k_prep_img<<<(STEPSC * IMG_ELEMS_PER_STEP + 255) / 256, 256>>>(W_hh);
    k_input<<<(N_NODESC + 63) / 64, 128>>>(x, W_in, (float*)hA);

    float* hcur = (float*)hA;
    float* hnext = (float*)hB;
    for (int s = 0; s < STEPSC; s++) {
        cudaMemsetAsync(aggPtr, 0, (size_t)N_NODESC * HC * sizeof(float), 0);
        k_scatter<<<(int)(((long long)N_EDGESC * 32 + 255) / 256), 256>>>(ei, hcur);
        dim3 grid(NTILES, 4);
        k_gemm<<<grid, 256, SMEM_DYN>>>(hcur, hnext,
                                        (const float*)wHiPtr + (size_t)s * IMG_STEP,
                                        (const float*)wLoPtr + (size_t)s * IMG_STEP,
                                        b_ih, b_hh);
        float* tmp = hcur; hcur = hnext; hnext = tmp;
    }
    cudaMemsetAsync(sumsPtr, 0, (size_t)N_GRAPHSC * HC * sizeof(float), 0);
    cudaMemsetAsync(cntPtr, 0, (size_t)N_GRAPHSC * sizeof(float), 0);
    k_pool<<<(int)(((long long)N_NODESC * 32 + 255) / 256), 256>>>(hcur, batch);
    k_out<<<N_GRAPHSC, 128>>>(W_p, b_p, out);
}

// round 6
// speedup vs baseline: 2.0496x; 2.0447x over previous
#include <cuda_runtime.h>
#include <cstdint>

#define N_NODESC 100000
#define N_EDGESC 1600000
#define N_GRAPHSC 512
#define F_INC 64
#define HC 128
#define H3C 384
#define STEPSC 6
#define NTILES ((N_NODESC + 127) / 128)
#define BP_TILE 1088                    // uint32 words per kt tile (8 pair-planes x 136)
#define BIMG_STEP (4 * 16 * BP_TILE)    // words per step per (hi|lo) image = 69632
#define BUF_W 4352                      // words per pipeline buffer: Ahi|Alo|Bhi|Blo
#define SMEM_DYN (2 * BUF_W * 4)        // 34816 bytes

// ---------------- device scratch ----------------
__device__ float g_hA[(size_t)N_NODESC * HC];
__device__ float g_hB[(size_t)N_NODESC * HC];
__device__ float g_agg[(size_t)N_NODESC * HC];
__device__ float g_WcG[(size_t)STEPSC * H3C * HC];      // grouped (r|z|n): [s][gate*128+f][k]
__device__ uint32_t g_WimgHi[(size_t)STEPSC * BIMG_STEP];  // bf16x2 hi image
__device__ uint32_t g_WimgLo[(size_t)STEPSC * BIMG_STEP];  // bf16x2 lo image
__device__ float g_sums[N_GRAPHSC * HC];
__device__ float g_cnt[N_GRAPHSC];
__device__ int   g_is64;
// CSR
__device__ int g_deg[N_NODESC];
__device__ int g_cursor[N_NODESC];
__device__ int g_rowstart[N_NODESC + 1];
__device__ int g_srcs[N_EDGESC];

// ---------------- helpers ----------------
__device__ __forceinline__ uint32_t smem_u32(const void* p) {
    uint32_t a;
    asm("{ .reg .u64 t; cvta.to.shared.u64 t, %1; cvt.u32.u64 %0, t; }" : "=r"(a) : "l"(p));
    return a;
}
__device__ __forceinline__ uint32_t pack_bf2(float lo, float hi) {
    uint32_t r;
    asm("cvt.rn.bf16x2.f32 %0, %1, %2;" : "=r"(r) : "f"(hi), "f"(lo));
    return r;
}
__device__ __forceinline__ float bf2_low(uint32_t v)  { return __uint_as_float(v << 16); }
__device__ __forceinline__ float bf2_high(uint32_t v) { return __uint_as_float(v & 0xffff0000u); }
__device__ __forceinline__ void red4(float* p, float4 v) {
    asm volatile("red.global.add.v4.f32 [%0], {%1,%2,%3,%4};"
                 :: "l"(p), "f"(v.x), "f"(v.y), "f"(v.z), "f"(v.w) : "memory");
}
__device__ __forceinline__ int load_idx(const void* p, long long i, int is64) {
    if (is64) return (int)((const long long*)p)[i];
    return ((const int*)p)[i];
}
__device__ __forceinline__ float sigf(float x) {
    return __fdividef(1.0f, 1.0f + __expf(-x));
}
__device__ __forceinline__ float tanhfast(float x) {
    float e = __expf(2.0f * x);
    return 1.0f - __fdividef(2.0f, e + 1.0f);
}
__device__ __forceinline__ void mma_bf16(float* d, uint32_t a0, uint32_t a1, uint32_t a2,
                                         uint32_t a3, uint32_t b0, uint32_t b1) {
    asm volatile(
        "mma.sync.aligned.m16n8k16.row.col.f32.bf16.bf16.f32 "
        "{%0,%1,%2,%3}, {%4,%5,%6,%7}, {%8,%9}, {%0,%1,%2,%3};"
        : "+f"(d[0]), "+f"(d[1]), "+f"(d[2]), "+f"(d[3])
        : "r"(a0), "r"(a1), "r"(a2), "r"(a3), "r"(b0), "r"(b1));
}
__device__ __forceinline__ void cpasync16(uint32_t saddr, const void* g) {
    asm volatile("cp.async.cg.shared.global [%0], [%1], 16;" :: "r"(saddr), "l"(g) : "memory");
}
__device__ __forceinline__ void cp_commit() { asm volatile("cp.async.commit_group;" ::: "memory"); }
__device__ __forceinline__ void cp_wait1()  { asm volatile("cp.async.wait_group 1;" ::: "memory"); }
__device__ __forceinline__ void cp_wait0()  { asm volatile("cp.async.wait_group 0;" ::: "memory"); }

// ---------------- index dtype sniffer ----------------
__global__ void k_detect(const int* __restrict__ ei) {
    int any = 0;
    for (int i = threadIdx.x; i < 2048; i += blockDim.x) any |= ei[2 * i + 1];
    any = __syncthreads_or(any);
    if (threadIdx.x == 0) g_is64 = (any == 0) ? 1 : 0;
}

// ---------------- CSR build ----------------
__global__ void k_deg(const void* __restrict__ ei) {
    int e = blockIdx.x * blockDim.x + threadIdx.x;
    if (e >= N_EDGESC) return;
    int d = load_idx(ei, (long long)N_EDGESC + e, g_is64);
    atomicAdd(&g_deg[d], 1);
}

__global__ void k_scan() {
    const int T = 1024;
    int tid = threadIdx.x;
    __shared__ int wsum[32];
    __shared__ int sbase;
    if (tid == 0) { sbase = 0; g_rowstart[0] = 0; }
    __syncthreads();
    for (int start = 0; start < N_NODESC; start += T) {
        int i = start + tid;
        int v = (i < N_NODESC) ? g_deg[i] : 0;
        int s = v;
#pragma unroll
        for (int o = 1; o < 32; o <<= 1) {
            int t = __shfl_up_sync(0xffffffffu, s, o);
            if ((tid & 31) >= o) s += t;
        }
        if ((tid & 31) == 31) wsum[tid >> 5] = s;
        __syncthreads();
        if (tid < 32) {
            int w = wsum[tid];
#pragma unroll
            for (int o = 1; o < 32; o <<= 1) {
                int t = __shfl_up_sync(0xffffffffu, w, o);
                if (tid >= o) w += t;
            }
            wsum[tid] = w;
        }
        __syncthreads();
        int add = (tid >= 32) ? wsum[(tid >> 5) - 1] : 0;
        int inc = sbase + add + s;
        if (i < N_NODESC) g_rowstart[i + 1] = inc;
        __syncthreads();
        if (tid == T - 1) sbase = inc;
        __syncthreads();
    }
}

__global__ void k_fill(const void* __restrict__ ei) {
    int e = blockIdx.x * blockDim.x + threadIdx.x;
    if (e >= N_EDGESC) return;
    int is64 = g_is64;
    int s = load_idx(ei, e, is64);
    int d = load_idx(ei, (long long)N_EDGESC + e, is64);
    int pos = g_rowstart[d] + atomicAdd(&g_cursor[d], 1);
    g_srcs[pos] = s;
}

// ---------------- gather: agg[n] = sum h[src] over in-edges ----------------
__global__ void k_gather(const float* __restrict__ h) {
    int w = (blockIdx.x * blockDim.x + threadIdx.x) >> 5;
    int lane = threadIdx.x & 31;
    if (w >= N_NODESC) return;
    int beg = g_rowstart[w], end = g_rowstart[w + 1];
    const float4* hb = (const float4*)h;
    float4 a0 = make_float4(0.f, 0.f, 0.f, 0.f);
    float4 a1 = make_float4(0.f, 0.f, 0.f, 0.f);
    int i = beg;
    for (; i + 2 <= end; i += 2) {
        int s0 = __ldg(&g_srcs[i]);
        int s1 = __ldg(&g_srcs[i + 1]);
        float4 v0 = hb[(size_t)s0 * 32 + lane];
        float4 v1 = hb[(size_t)s1 * 32 + lane];
        a0.x += v0.x; a0.y += v0.y; a0.z += v0.z; a0.w += v0.w;
        a1.x += v1.x; a1.y += v1.y; a1.z += v1.z; a1.w += v1.w;
    }
    if (i < end) {
        int s0 = __ldg(&g_srcs[i]);
        float4 v0 = hb[(size_t)s0 * 32 + lane];
        a0.x += v0.x; a0.y += v0.y; a0.z += v0.z; a0.w += v0.w;
    }
    a0.x += a1.x; a0.y += a1.y; a0.z += a1.z; a0.w += a1.w;
    ((float4*)g_agg)[(size_t)w * 32 + lane] = a0;
}

// ---------------- weight precompute ----------------
// WcG[s][gate*128+f][k] = sum_m Wmp[s][k][m] * Wih[gate*128+f][m]
__global__ void k_prep_wc(const float* __restrict__ Wmp, const float* __restrict__ Wih) {
    int idx = blockIdx.x * blockDim.x + threadIdx.x;
    if (idx >= STEPSC * H3C * HC) return;
    int k = idx % HC;
    int j = (idx / HC) % H3C;
    int s = idx / (HC * H3C);
    const float4* wm = (const float4*)(Wmp + ((size_t)s * HC + k) * HC);
    const float4* wi = (const float4*)(Wih + (size_t)j * HC);
    float acc = 0.f;
#pragma unroll
    for (int m = 0; m < HC / 4; m++) {
        float4 a = wm[m], b = wi[m];
        acc += a.x * b.x + a.y * b.y + a.z * b.z + a.w * b.w;
    }
    g_WcG[idx] = acc;
}

// Build bf16x2 pair-plane images of Wbig[256][512], hi + lo split.
// Image layout: [s][ys][kt][p 0..7][col 0..135]; element = pair (k=kt*16+2p, +1).
// col<128 real (colg = ys*128+col; f=colg>>2; gate=colg&3), col>=128 zero pad.
__global__ void k_prep_img(const float* __restrict__ Whh) {
    int idx = blockIdx.x * blockDim.x + threadIdx.x;
    if (idx >= STEPSC * BIMG_STEP) return;
    int col = idx % 136;
    int t = idx / 136;
    int p = t & 7; t >>= 3;
    int kt = t & 15; t >>= 4;
    int ys = t & 3;
    int s = t >> 2;
    float v0 = 0.f, v1 = 0.f;
    if (col < 128) {
        int colg = ys * 128 + col;
        int f = colg >> 2, gate = colg & 3;
        int k0 = kt * 16 + 2 * p;
#pragma unroll
        for (int e = 0; e < 2; e++) {
            int k = k0 + e;
            float val;
            if (k < HC) {
                val = (gate < 3) ? g_WcG[((size_t)s * H3C + gate * HC + f) * HC + k] : 0.f;
            } else {
                int g2 = (gate == 3) ? 2 : gate;
                val = Whh[(size_t)(g2 * HC + f) * HC + (k - HC)];
            }
            if (e == 0) v0 = val; else v1 = val;
        }
    }
    uint32_t hi = pack_bf2(v0, v1);
    float r0 = v0 - bf2_low(hi);
    float r1 = v1 - bf2_high(hi);
    uint32_t lo = pack_bf2(r0, r1);
    g_WimgHi[idx] = hi;
    g_WimgLo[idx] = lo;
}

// ---------------- input layer: h = tanh(x @ W_in) ----------------
__global__ void k_input(const float* __restrict__ x, const float* __restrict__ Win,
                        float* __restrict__ h) {
    __shared__ float sw[F_INC * HC];
    __shared__ float sx[4][F_INC];
    int tid = threadIdx.x;  // 128
    for (int i = tid; i < F_INC * HC; i += 128) sw[i] = Win[i];
    int base = blockIdx.x * 64;
    for (int n0 = 0; n0 < 64; n0 += 4) {
        __syncthreads();
        for (int i = tid; i < 4 * F_INC; i += 128) {
            int ni = i / F_INC, k = i % F_INC;
            int node = base + n0 + ni;
            sx[ni][k] = (node < N_NODESC) ? x[(size_t)node * F_INC + k] : 0.f;
        }
        __syncthreads();
        float a0 = 0, a1 = 0, a2 = 0, a3 = 0;
#pragma unroll
        for (int k = 0; k < F_INC; k++) {
            float w = sw[k * HC + tid];
            a0 += sx[0][k] * w; a1 += sx[1][k] * w;
            a2 += sx[2][k] * w; a3 += sx[3][k] * w;
        }
        int node = base + n0;
        if (node + 0 < N_NODESC) h[(size_t)(node + 0) * HC + tid] = tanhf(a0);
        if (node + 1 < N_NODESC) h[(size_t)(node + 1) * HC + tid] = tanhf(a1);
        if (node + 2 < N_NODESC) h[(size_t)(node + 2) * HC + tid] = tanhf(a2);
        if (node + 3 < N_NODESC) h[(size_t)(node + 3) * HC + tid] = tanhf(a3);
    }
}

// ---------------- bf16x3 mma.sync fused GEMM + GRU ----------------
// CTA tile: 128 rows x 128 cols (32 features x 4 gates interleaved). K=256 ([agg|h]).
// acc = Ahi*Bhi + Ahi*Blo + Alo*Bhi, bf16 splits (effective ~2^-16/product).
__global__ void __launch_bounds__(256) k_gemm(
    const float* __restrict__ hin, float* __restrict__ hout,
    const uint32_t* __restrict__ WimgHi, const uint32_t* __restrict__ WimgLo,
    const float* __restrict__ bih, const float* __restrict__ bhh)
{
    extern __shared__ uint32_t smu[];  // [2][Ahi 1088|Alo 1088|Bhi 1088|Blo 1088]
    __shared__ float sbias[4][32];

    const int tid = threadIdx.x;
    const int lane = tid & 31;
    const int warp = tid >> 5;
    const int warpM = warp & 1;
    const int warpN = warp >> 1;
    const int g = lane >> 2;
    const int tI = lane & 3;
    const int row0 = blockIdx.x * 128;
    const int ys = blockIdx.y;

    if (tid < 32) {
        int f = ys * 32 + tid;
        sbias[0][tid] = bih[f] + bhh[f];
        sbias[1][tid] = bih[HC + f] + bhh[HC + f];
        sbias[2][tid] = bih[2 * HC + f];
        sbias[3][tid] = bhh[2 * HC + f];
    }

    const uint32_t* WHi = WimgHi + (size_t)ys * 16 * BP_TILE;
    const uint32_t* WLo = WimgLo + (size_t)ys * 16 * BP_TILE;

    float acc[4][4][4];
#pragma unroll
    for (int mt = 0; mt < 4; mt++)
#pragma unroll
        for (int nt = 0; nt < 4; nt++)
#pragma unroll
            for (int r = 0; r < 4; r++) acc[mt][nt][r] = 0.f;

    // ---- B tile async copy: 272 hi + 272 lo 16B chunks ----
    auto issueB = [&](int kt) {
        uint32_t bB = smem_u32(smu) + ((kt & 1) * BUF_W + 2 * BP_TILE) * 4;
        const float4* hi4 = (const float4*)(WHi + (size_t)kt * BP_TILE);
        const float4* lo4 = (const float4*)(WLo + (size_t)kt * BP_TILE);
#pragma unroll
        for (int rep = 0; rep < 2; rep++) {
            int idx = tid + rep * 256;
            if (idx < 544) {
                const float4* src = (idx < 272) ? (hi4 + idx) : (lo4 + (idx - 272) - 272 + 272);
                // hi chunks go to words [0,1088), lo to [1088,2176)
                const float4* s2 = (idx < 272) ? (hi4 + idx) : (lo4 + (idx - 272));
                cpasync16(bB + idx * 16, s2);
                (void)src;
            }
        }
        if (tid < 32) {
            int idx = 512 + tid;
            cpasync16(bB + idx * 16, (const float4*)(WLo + (size_t)kt * BP_TILE) + (idx - 272));
        }
        cp_commit();
    };

    float4 av[2];
    auto loadA = [&](int kt) {
        const float* Asrc = (kt < 8) ? g_agg : hin;
        int colb = (kt & 7) * 16;
#pragma unroll
        for (int rep = 0; rep < 2; rep++) {
            int idx = tid + rep * 256;
            int row = idx >> 2, kq = idx & 3;
            int grow = row0 + row;
            av[rep] = (grow < N_NODESC)
                ? *(const float4*)(Asrc + (size_t)grow * HC + colb + kq * 4)
                : make_float4(0.f, 0.f, 0.f, 0.f);
        }
    };

    issueB(0);
    loadA(0);

    for (int kt = 0; kt < 16; kt++) {
        uint32_t* buf = smu + (kt & 1) * BUF_W;
        uint32_t* bufAhi = buf;
        uint32_t* bufAlo = buf + BP_TILE;
        uint32_t* bufBhi = buf + 2 * BP_TILE;
        uint32_t* bufBlo = buf + 3 * BP_TILE;

        // STS A split (bf16 hi/lo pairs): planes p = 2kq, 2kq+1
#pragma unroll
        for (int rep = 0; rep < 2; rep++) {
            int idx = tid + rep * 256;
            int row = idx >> 2, kq = idx & 3;
            float4 v = av[rep];
            uint32_t h0 = pack_bf2(v.x, v.y);
            uint32_t h1 = pack_bf2(v.z, v.w);
            uint32_t l0 = pack_bf2(v.x - bf2_low(h0), v.y - bf2_high(h0));
            uint32_t l1 = pack_bf2(v.z - bf2_low(h1), v.w - bf2_high(h1));
            int base = 272 * kq + row;
            bufAhi[base] = h0;
            bufAhi[base + 136] = h1;
            bufAlo[base] = l0;
            bufAlo[base + 136] = l1;
        }

        if (kt < 15) { issueB(kt + 1); cp_wait1(); }
        else cp_wait0();
        __syncthreads();

        if (kt < 15) loadA(kt + 1);

        // compute: one k16 step, 3 terms
        uint32_t bh[4][2], bl[4][2];
        int bcol = warpN * 32 + g;
#pragma unroll
        for (int nt = 0; nt < 4; nt++) {
            int boff = tI * 136 + bcol + nt * 8;
            bh[nt][0] = bufBhi[boff];
            bh[nt][1] = bufBhi[boff + 544];
            bl[nt][0] = bufBlo[boff];
            bl[nt][1] = bufBlo[boff + 544];
        }
#pragma unroll
        for (int mt = 0; mt < 4; mt++) {
            int aoff = tI * 136 + warpM * 64 + mt * 16 + g;
            uint32_t ah0 = bufAhi[aoff];
            uint32_t ah1 = bufAhi[aoff + 8];
            uint32_t ah2 = bufAhi[aoff + 544];
            uint32_t ah3 = bufAhi[aoff + 544 + 8];
            uint32_t al0 = bufAlo[aoff];
            uint32_t al1 = bufAlo[aoff + 8];
            uint32_t al2 = bufAlo[aoff + 544];
            uint32_t al3 = bufAlo[aoff + 544 + 8];
#pragma unroll
            for (int nt = 0; nt < 4; nt++) {
                mma_bf16(acc[mt][nt], ah0, ah1, ah2, ah3, bh[nt][0], bh[nt][1]);
                mma_bf16(acc[mt][nt], ah0, ah1, ah2, ah3, bl[nt][0], bl[nt][1]);
                mma_bf16(acc[mt][nt], al0, al1, al2, al3, bh[nt][0], bh[nt][1]);
            }
        }
        __syncthreads();
    }

    // ---------------- fused GRU epilogue (D layout same as k8 tf32) ----------------
    float* sOut = (float*)smu;  // [128][36]
    const int odd = tI & 1;
    const int fl = warpN * 8 + (tI >> 1);

#pragma unroll
    for (int mt = 0; mt < 4; mt++) {
#pragma unroll
        for (int nt = 0; nt < 4; nt++) {
            float c0 = acc[mt][nt][0], c1 = acc[mt][nt][1];
            float c2 = acc[mt][nt][2], c3 = acc[mt][nt][3];
            float x0 = __shfl_xor_sync(0xffffffffu, c0, 1);
            float x1 = __shfl_xor_sync(0xffffffffu, c1, 1);
            float x2 = __shfl_xor_sync(0xffffffffu, c2, 1);
            float x3 = __shfl_xor_sync(0xffffffffu, c3, 1);
            float Sr = odd ? x2 : c0;
            float Sz = odd ? x3 : c1;
            float Sn = odd ? c2 : x0;
            float hn = odd ? c3 : x1;
            int rowl = warpM * 64 + mt * 16 + g + (odd ? 8 : 0);
            int f = fl + nt * 2;
            int grow = row0 + rowl;
            float hprev = (grow < N_NODESC) ? hin[(size_t)grow * HC + ys * 32 + f] : 0.f;
            float rr = sigf(Sr + sbias[0][f]);
            float zz = sigf(Sz + sbias[1][f]);
            float nn = tanhfast(Sn - hn + sbias[2][f] + rr * (hn + sbias[3][f]));
            sOut[rowl * 36 + f] = (1.f - zz) * nn + zz * hprev;
        }
    }
    __syncthreads();
#pragma unroll
    for (int rep = 0; rep < 4; rep++) {
        int idx = tid + rep * 256;
        int row = idx >> 3, q = idx & 7;
        int grow = row0 + row;
        if (grow < N_NODESC)
            *(float4*)(hout + (size_t)grow * HC + ys * 32 + q * 4) =
                *(const float4*)(sOut + row * 36 + q * 4);
    }
}

// ---------------- pooling ----------------
__global__ void k_pool(const float* __restrict__ h, const void* __restrict__ batch) {
    int w = (blockIdx.x * blockDim.x + threadIdx.x) >> 5;
    int lane = threadIdx.x & 31;
    if (w >= N_NODESC) return;
    int g = load_idx(batch, w, g_is64);
    float4 v = *((const float4*)(h + (size_t)w * HC) + lane);
    float* p = (float*)((float4*)(g_sums + (size_t)g * HC) + lane);
    red4(p, v);
    if (lane == 0) atomicAdd(&g_cnt[g], 1.0f);
}

__global__ void k_out(const float* __restrict__ Wp, const float* __restrict__ bp,
                      float* __restrict__ out) {
    int g = blockIdx.x;
    int t = threadIdx.x;  // 128
    float c = fmaxf(g_cnt[g], 1.0f);
    float pooled = g_sums[g * HC + t] / c;
    float v = fmaxf(pooled, 0.f) * Wp[t];
    __shared__ float red[4];
#pragma unroll
    for (int o = 16; o > 0; o >>= 1) v += __shfl_down_sync(0xffffffff, v, o);
    if ((t & 31) == 0) red[t >> 5] = v;
    __syncthreads();
    if (t == 0) out[g] = red[0] + red[1] + red[2] + red[3] + bp[0];
}

// ---------------- launch ----------------
extern "C" void kernel_launch(void* const* d_in, const int* in_sizes, int n_in,
                              void* d_out, int out_size) {
    const float* x    = (const float*)d_in[0];
    const void*  ei   = d_in[1];
    const void*  batch= d_in[2];
    const float* W_in = (const float*)d_in[3];
    const float* W_mp = (const float*)d_in[4];
    const float* W_ih = (const float*)d_in[5];
    const float* W_hh = (const float*)d_in[6];
    const float* b_ih = (const float*)d_in[7];
    const float* b_hh = (const float*)d_in[8];
    const float* W_p  = (const float*)d_in[9];
    const float* b_p  = (const float*)d_in[10];
    float* out = (float*)d_out;

    void *hA, *hB, *sumsPtr, *cntPtr, *wHiPtr, *wLoPtr, *degPtr, *curPtr;
    cudaGetSymbolAddress(&hA, g_hA);
    cudaGetSymbolAddress(&hB, g_hB);
    cudaGetSymbolAddress(&sumsPtr, g_sums);
    cudaGetSymbolAddress(&cntPtr, g_cnt);
    cudaGetSymbolAddress(&wHiPtr, g_WimgHi);
    cudaGetSymbolAddress(&wLoPtr, g_WimgLo);
    cudaGetSymbolAddress(&degPtr, g_deg);
    cudaGetSymbolAddress(&curPtr, g_cursor);

    k_detect<<<1, 256>>>((const int*)ei);

    // CSR build (once per launch)
    cudaMemsetAsync(degPtr, 0, N_NODESC * sizeof(int), 0);
    cudaMemsetAsync(curPtr, 0, N_NODESC * sizeof(int), 0);
    k_deg<<<(N_EDGESC + 255) / 256, 256>>>(ei);
    k_scan<<<1, 1024>>>();
    k_fill<<<(N_EDGESC + 255) / 256, 256>>>(ei);

    // weights
    k_prep_wc<<<(STEPSC * H3C * HC + 255) / 256, 256>>>(W_mp, W_ih);
    k_prep_img<<<(STEPSC * BIMG_STEP + 255) / 256, 256>>>(W_hh);

    k_input<<<(N_NODESC + 63) / 64, 128>>>(x, W_in, (float*)hA);

    float* hcur = (float*)hA;
    float* hnext = (float*)hB;
    for (int s = 0; s < STEPSC; s++) {
        k_gather<<<(int)(((long long)N_NODESC * 32 + 255) / 256), 256>>>(hcur);
        dim3 grid(NTILES, 4);
        k_gemm<<<grid, 256, SMEM_DYN>>>(hcur, hnext,
                                        (const uint32_t*)wHiPtr + (size_t)s * BIMG_STEP,
                                        (const uint32_t*)wLoPtr + (size_t)s * BIMG_STEP,
                                        b_ih, b_hh);
        float* tmp = hcur; hcur = hnext; hnext = tmp;
    }
    cudaMemsetAsync(sumsPtr, 0, (size_t)N_GRAPHSC * HC * sizeof(float), 0);
    cudaMemsetAsync(cntPtr, 0, (size_t)N_GRAPHSC * sizeof(float), 0);
    k_pool<<<(int)(((long long)N_NODESC * 32 + 255) / 256), 256>>>(hcur, batch);
    k_out<<<N_GRAPHSC, 128>>>(W_p, b_p, out);
}

// round 8
// speedup vs baseline: 2.2358x; 1.0908x over previous
#include <cuda_runtime.h>
#include <cstdint>

#define N_NODESC 100000
#define N_EDGESC 1600000
#define N_GRAPHSC 512
#define F_INC 64
#define HC 128
#define H3C 384
#define STEPSC 6
#define NTILES 782                         // ceil(100000/128)
#define AIMG_WORDS ((size_t)NTILES * 8 * 1024)
#define BIMG_STEP_W (4 * 16 * 1024)        // 65536 words per step per image
#define STAGE_W 4096                       // words per pipeline stage: Ahi|Alo|Bhi|Blo
#define SMEM_DYN (3 * STAGE_W * 4)         // 49152 B
#define NSCANB 98                          // ceil(100000/1024)

// ---------------- device scratch ----------------
__device__ float g_hA[(size_t)N_NODESC * HC];
__device__ float g_hB[(size_t)N_NODESC * HC];
__device__ float g_WcG[(size_t)STEPSC * H3C * HC];
__device__ __align__(16) uint32_t g_AHi[AIMG_WORDS];     // agg fragment image (bf16x2 hi)
__device__ __align__(16) uint32_t g_ALo[AIMG_WORDS];
__device__ __align__(16) uint32_t g_HHi[2][AIMG_WORDS];  // h fragment images, step parity
__device__ __align__(16) uint32_t g_HLo[2][AIMG_WORDS];
__device__ __align__(16) uint32_t g_BHi[(size_t)STEPSC * BIMG_STEP_W];
__device__ __align__(16) uint32_t g_BLo[(size_t)STEPSC * BIMG_STEP_W];
__device__ float g_sums[N_GRAPHSC * HC];
__device__ float g_cnt[N_GRAPHSC];
__device__ int   g_is64;
// CSR
__device__ int g_deg[N_NODESC];
__device__ int g_cursor[N_NODESC];
__device__ int g_rowstart[N_NODESC + 1];
__device__ int g_srcs[N_EDGESC];
__device__ int g_bsum[NSCANB];

// ---------------- helpers ----------------
__device__ __forceinline__ uint32_t smem_u32(const void* p) {
    uint32_t a;
    asm("{ .reg .u64 t; cvta.to.shared.u64 t, %1; cvt.u32.u64 %0, t; }" : "=r"(a) : "l"(p));
    return a;
}
__device__ __forceinline__ uint32_t pack_bf2(float lo, float hi) {
    uint32_t r;
    asm("cvt.rn.bf16x2.f32 %0, %1, %2;" : "=r"(r) : "f"(hi), "f"(lo));
    return r;
}
__device__ __forceinline__ float bf2_low(uint32_t v)  { return __uint_as_float(v << 16); }
__device__ __forceinline__ float bf2_high(uint32_t v) { return __uint_as_float(v & 0xffff0000u); }
__device__ __forceinline__ void red4(float* p, float4 v) {
    asm volatile("red.global.add.v4.f32 [%0], {%1,%2,%3,%4};"
                 :: "l"(p), "f"(v.x), "f"(v.y), "f"(v.z), "f"(v.w) : "memory");
}
__device__ __forceinline__ int load_idx(const void* p, long long i, int is64) {
    if (is64) return (int)((const long long*)p)[i];
    return ((const int*)p)[i];
}
__device__ __forceinline__ float sigf(float x) {
    return __fdividef(1.0f, 1.0f + __expf(-x));
}
__device__ __forceinline__ float tanhfast(float x) {
    float e = __expf(2.0f * x);
    return 1.0f - __fdividef(2.0f, e + 1.0f);
}
__device__ __forceinline__ void mma_bf16(float* d, uint32_t a0, uint32_t a1, uint32_t a2,
                                         uint32_t a3, uint32_t b0, uint32_t b1) {
    asm volatile(
        "mma.sync.aligned.m16n8k16.row.col.f32.bf16.bf16.f32 "
        "{%0,%1,%2,%3}, {%4,%5,%6,%7}, {%8,%9}, {%0,%1,%2,%3};"
        : "+f"(d[0]), "+f"(d[1]), "+f"(d[2]), "+f"(d[3])
        : "r"(a0), "r"(a1), "r"(a2), "r"(a3), "r"(b0), "r"(b1));
}
__device__ __forceinline__ void cpasync16(uint32_t saddr, const void* g) {
    asm volatile("cp.async.cg.shared.global [%0], [%1], 16;" :: "r"(saddr), "l"(g) : "memory");
}
__device__ __forceinline__ void cp_commit() { asm volatile("cp.async.commit_group;" ::: "memory"); }
__device__ __forceinline__ void cp_wait1()  { asm volatile("cp.async.wait_group 1;" ::: "memory"); }
__device__ __forceinline__ void cp_wait0()  { asm volatile("cp.async.wait_group 0;" ::: "memory"); }

// Fragment-image word offset for (row-in-tile rr, pair p) within a [tile][kt] 1024-word block.
__device__ __forceinline__ int aimg_word(int rr, int p) {
    int g = rr & 7, rh = (rr >> 3) & 1, rb = rr >> 4;
    return rb * 128 + (g * 4 + (p & 3)) * 4 + (p >> 2) * 2 + rh;
}

// Split a float4 (4 consecutive k at even offset) into 2 hi + 2 lo bf16x2 words and
// store to image at pairs p0, p0+1.
__device__ __forceinline__ void store_split4(uint32_t* Hi, uint32_t* Lo, size_t base,
                                             int rr, int p0, float4 v) {
    uint32_t h0 = pack_bf2(v.x, v.y);
    uint32_t h1 = pack_bf2(v.z, v.w);
    uint32_t l0 = pack_bf2(v.x - bf2_low(h0), v.y - bf2_high(h0));
    uint32_t l1 = pack_bf2(v.z - bf2_low(h1), v.w - bf2_high(h1));
    int w0 = aimg_word(rr, p0), w1 = aimg_word(rr, p0 + 1);
    Hi[base + w0] = h0; Hi[base + w1] = h1;
    Lo[base + w0] = l0; Lo[base + w1] = l1;
}

// ---------------- index dtype sniffer ----------------
__global__ void k_detect(const int* __restrict__ ei) {
    int any = 0;
    for (int i = threadIdx.x; i < 2048; i += blockDim.x) any |= ei[2 * i + 1];
    any = __syncthreads_or(any);
    if (threadIdx.x == 0) g_is64 = (any == 0) ? 1 : 0;
}

// ---------------- CSR build ----------------
__global__ void k_deg(const void* __restrict__ ei) {
    int e = blockIdx.x * blockDim.x + threadIdx.x;
    if (e >= N_EDGESC) return;
    int d = load_idx(ei, (long long)N_EDGESC + e, g_is64);
    atomicAdd(&g_deg[d], 1);
}

__global__ void k_scan1() {
    __shared__ int sred[8];
    int b = blockIdx.x, t = threadIdx.x;
    int i0 = b * 1024 + t * 4;
    int s = 0;
#pragma unroll
    for (int j = 0; j < 4; j++) {
        int i = i0 + j;
        if (i < N_NODESC) s += g_deg[i];
    }
#pragma unroll
    for (int o = 16; o > 0; o >>= 1) s += __shfl_down_sync(0xffffffffu, s, o);
    if ((t & 31) == 0) sred[t >> 5] = s;
    __syncthreads();
    if (t == 0) {
        int tot = 0;
#pragma unroll
        for (int j = 0; j < 8; j++) tot += sred[j];
        g_bsum[b] = tot;
    }
}

__global__ void k_scan2() {
    int lane = threadIdx.x;  // 32
    int base = 0;
    for (int c = 0; c < 4; c++) {
        int i = c * 32 + lane;
        int v = (i < NSCANB) ? g_bsum[i] : 0;
        int s = v;
#pragma unroll
        for (int o = 1; o < 32; o <<= 1) {
            int t = __shfl_up_sync(0xffffffffu, s, o);
            if (lane >= o) s += t;
        }
        if (i < NSCANB) g_bsum[i] = base + (s - v);  // exclusive
        base += __shfl_sync(0xffffffffu, s, 31);
    }
    if (lane == 0) g_rowstart[0] = 0;
}

__global__ void k_scan3() {
    __shared__ int swarp[8];
    int b = blockIdx.x, t = threadIdx.x;
    int i0 = b * 1024 + t * 4;
    int d[4], ts = 0;
#pragma unroll
    for (int j = 0; j < 4; j++) {
        d[j] = (i0 + j < N_NODESC) ? g_deg[i0 + j] : 0;
        ts += d[j];
    }
    int s = ts;
#pragma unroll
    for (int o = 1; o < 32; o <<= 1) {
        int v = __shfl_up_sync(0xffffffffu, s, o);
        if ((t & 31) >= o) s += v;
    }
    if ((t & 31) == 31) swarp[t >> 5] = s;
    __syncthreads();
    int wpre = 0;
    for (int j = 0; j < (t >> 5); j++) wpre += swarp[j];
    int run = g_bsum[b] + wpre + (s - ts);
#pragma unroll
    for (int j = 0; j < 4; j++) {
        run += d[j];
        if (i0 + j < N_NODESC) g_rowstart[i0 + j + 1] = run;
    }
}

__global__ void k_fill(const void* __restrict__ ei) {
    int e = blockIdx.x * blockDim.x + threadIdx.x;
    if (e >= N_EDGESC) return;
    int is64 = g_is64;
    int s = load_idx(ei, e, is64);
    int d = load_idx(ei, (long long)N_EDGESC + e, is64);
    int pos = g_rowstart[d] + atomicAdd(&g_cursor[d], 1);
    g_srcs[pos] = s;
}

// ---------------- gather: agg[n] = sum h[src]; write fragment images ----------------
__global__ void k_gather(const float* __restrict__ h) {
    int w = (blockIdx.x * blockDim.x + threadIdx.x) >> 5;
    int lane = threadIdx.x & 31;
    if (w >= N_NODESC) return;
    int beg = g_rowstart[w], end = g_rowstart[w + 1];
    const float4* hb = (const float4*)h;
    float4 a0 = make_float4(0.f, 0.f, 0.f, 0.f);
    float4 a1 = make_float4(0.f, 0.f, 0.f, 0.f);
    int i = beg;
    for (; i + 2 <= end; i += 2) {
        int s0 = __ldg(&g_srcs[i]);
        int s1 = __ldg(&g_srcs[i + 1]);
        float4 v0 = hb[(size_t)s0 * 32 + lane];
        float4 v1 = hb[(size_t)s1 * 32 + lane];
        a0.x += v0.x; a0.y += v0.y; a0.z += v0.z; a0.w += v0.w;
        a1.x += v1.x; a1.y += v1.y; a1.z += v1.z; a1.w += v1.w;
    }
    if (i < end) {
        int s0 = __ldg(&g_srcs[i]);
        float4 v0 = hb[(size_t)s0 * 32 + lane];
        a0.x += v0.x; a0.y += v0.y; a0.z += v0.z; a0.w += v0.w;
    }
    a0.x += a1.x; a0.y += a1.y; a0.z += a1.z; a0.w += a1.w;
    int tile = w >> 7, rr = w & 127;
    int kt = lane >> 2, p0 = (lane & 3) * 2;
    size_t base = ((size_t)tile * 8 + kt) * 1024;
    store_split4(g_AHi, g_ALo, base, rr, p0, a0);
}

// ---------------- h -> fragment images (step 0 only) ----------------
__global__ void k_h2img(const float* __restrict__ h, uint32_t* __restrict__ Hi,
                        uint32_t* __restrict__ Lo) {
    int w = (blockIdx.x * blockDim.x + threadIdx.x) >> 5;
    int lane = threadIdx.x & 31;
    if (w >= N_NODESC) return;
    float4 v = ((const float4*)h)[(size_t)w * 32 + lane];
    int tile = w >> 7, rr = w & 127;
    int kt = lane >> 2, p0 = (lane & 3) * 2;
    size_t base = ((size_t)tile * 8 + kt) * 1024;
    store_split4(Hi, Lo, base, rr, p0, v);
}

// ---------------- weight precompute ----------------
__global__ void k_prep_wc(const float* __restrict__ Wmp, const float* __restrict__ Wih) {
    int idx = blockIdx.x * blockDim.x + threadIdx.x;
    if (idx >= STEPSC * H3C * HC) return;
    int k = idx % HC;
    int j = (idx / HC) % H3C;
    int s = idx / (HC * H3C);
    const float4* wm = (const float4*)(Wmp + ((size_t)s * HC + k) * HC);
    const float4* wi = (const float4*)(Wih + (size_t)j * HC);
    float acc = 0.f;
#pragma unroll
    for (int m = 0; m < HC / 4; m++) {
        float4 a = wm[m], b = wi[m];
        acc += a.x * b.x + a.y * b.y + a.z * b.z + a.w * b.w;
    }
    g_WcG[idx] = acc;
}

// B fragment images: [s][ys][kt][nb][lane][j]. col = ys*128 + nb*8 + (lane>>2);
// j=0 -> k pair (lane&3), j=1 -> pair (lane&3)+4 within the kt chunk.
__global__ void k_prep_bimg(const float* __restrict__ Whh) {
    int idx = blockIdx.x * blockDim.x + threadIdx.x;
    if (idx >= STEPSC * BIMG_STEP_W) return;
    int j   = idx & 1;
    int lane = (idx >> 1) & 31;
    int nb  = (idx >> 6) & 15;
    int kt  = (idx >> 10) & 15;
    int ys  = (idx >> 14) & 3;
    int s   = idx >> 16;
    int g = lane >> 2, tI = lane & 3;
    int colg = ys * 128 + nb * 8 + g;
    int f = colg >> 2, gate = colg & 3;
    int k0 = kt * 16 + 2 * tI + 8 * j;
    float v[2];
#pragma unroll
    for (int e = 0; e < 2; e++) {
        int k = k0 + e;
        float val;
        if (k < HC) {
            val = (gate < 3) ? g_WcG[((size_t)s * H3C + gate * HC + f) * HC + k] : 0.f;
        } else {
            int g2 = (gate == 3) ? 2 : gate;
            val = Whh[(size_t)(g2 * HC + f) * HC + (k - HC)];
        }
        v[e] = val;
    }
    uint32_t hi = pack_bf2(v[0], v[1]);
    uint32_t lo = pack_bf2(v[0] - bf2_low(hi), v[1] - bf2_high(hi));
    g_BHi[idx] = hi;
    g_BLo[idx] = lo;
}

// ---------------- input layer: h = tanh(x @ W_in) ----------------
__global__ void k_input(const float* __restrict__ x, const float* __restrict__ Win,
                        float* __restrict__ h) {
    __shared__ float sw[F_INC * HC];
    __shared__ float sx[4][F_INC];
    int tid = threadIdx.x;  // 128
    for (int i = tid; i < F_INC * HC; i += 128) sw[i] = Win[i];
    int base = blockIdx.x * 64;
    for (int n0 = 0; n0 < 64; n0 += 4) {
        __syncthreads();
        for (int i = tid; i < 4 * F_INC; i += 128) {
            int ni = i / F_INC, k = i % F_INC;
            int node = base + n0 + ni;
            sx[ni][k] = (node < N_NODESC) ? x[(size_t)node * F_INC + k] : 0.f;
        }
        __syncthreads();
        float a0 = 0, a1 = 0, a2 = 0, a3 = 0;
#pragma unroll
        for (int k = 0; k < F_INC; k++) {
            float w = sw[k * HC + tid];
            a0 += sx[0][k] * w; a1 += sx[1][k] * w;
            a2 += sx[2][k] * w; a3 += sx[3][k] * w;
        }
        int node = base + n0;
        if (node + 0 < N_NODESC) h[(size_t)(node + 0) * HC + tid] = tanhf(a0);
        if (node + 1 < N_NODESC) h[(size_t)(node + 1) * HC + tid] = tanhf(a1);
        if (node + 2 < N_NODESC) h[(size_t)(node + 2) * HC + tid] = tanhf(a2);
        if (node + 3 < N_NODESC) h[(size_t)(node + 3) * HC + tid] = tanhf(a3);
    }
}

// ---------------- bf16x3 mma.sync fused GEMM + GRU, all-cp.async operands ----------------
// Pipeline order per kt (CUTLASS-canonical): wait -> __syncthreads -> issue -> compute.
// The barrier after the wait makes ALL threads' group-kt copies visible before any read,
// and guarantees all threads finished compute(kt-1) before stage (kt-1)%3 is overwritten.
__global__ void __launch_bounds__(256, 2) k_gemm(
    const float* __restrict__ hin, float* __restrict__ hout,
    const uint32_t* __restrict__ Bhi, const uint32_t* __restrict__ Blo,
    const uint32_t* __restrict__ HhiIn, const uint32_t* __restrict__ HloIn,
    uint32_t* __restrict__ HhiOut, uint32_t* __restrict__ HloOut,
    const float* __restrict__ bih, const float* __restrict__ bhh, int write_img)
{
    extern __shared__ uint32_t smu[];  // 3 stages x [Ahi|Alo|Bhi|Blo] x 1024 words
    __shared__ float sbias[4][32];

    const int tid = threadIdx.x;
    const int lane = tid & 31;
    const int warp = tid >> 5;
    const int warpM = warp & 1;
    const int warpN = warp >> 1;
    const int tile = blockIdx.x;
    const int row0 = tile * 128;
    const int ys = blockIdx.y;

    if (tid < 32) {
        int f = ys * 32 + tid;
        sbias[0][tid] = bih[f] + bhh[f];
        sbias[1][tid] = bih[HC + f] + bhh[HC + f];
        sbias[2][tid] = bih[2 * HC + f];
        sbias[3][tid] = bhh[2 * HC + f];
    }

    const uint32_t* Bh = Bhi + (size_t)ys * 16 * 1024;
    const uint32_t* Bl = Blo + (size_t)ys * 16 * 1024;
    const uint32_t smem_base = smem_u32(smu);

    auto issue = [&](int kt) {
        uint32_t d = smem_base + ((kt % 3) * STAGE_W) * 4;
        const uint32_t *ah, *al;
        if (kt < 8) {
            ah = g_AHi + ((size_t)tile * 8 + kt) * 1024;
            al = g_ALo + ((size_t)tile * 8 + kt) * 1024;
        } else {
            ah = HhiIn + ((size_t)tile * 8 + (kt - 8)) * 1024;
            al = HloIn + ((size_t)tile * 8 + (kt - 8)) * 1024;
        }
        cpasync16(d + tid * 16,         ah + tid * 4);
        cpasync16(d + 4096 + tid * 16,  al + tid * 4);
        cpasync16(d + 8192 + tid * 16,  Bh + (size_t)kt * 1024 + tid * 4);
        cpasync16(d + 12288 + tid * 16, Bl + (size_t)kt * 1024 + tid * 4);
        cp_commit();
    };

    float acc[4][4][4];
#pragma unroll
    for (int mt = 0; mt < 4; mt++)
#pragma unroll
        for (int nt = 0; nt < 4; nt++)
#pragma unroll
            for (int r = 0; r < 4; r++) acc[mt][nt][r] = 0.f;

    issue(0);
    issue(1);

    for (int kt = 0; kt < 16; kt++) {
        if (kt < 15) cp_wait1();       // pending {kt, kt+1} -> group kt complete
        else cp_wait0();               // tail: everything complete
        __syncthreads();               // group-kt data visible to ALL; compute(kt-1) done by ALL
        if (kt <= 13) issue(kt + 2);   // safe: writes stage (kt-1)%3, all readers finished

        const uint32_t* st = smu + (kt % 3) * STAGE_W;
        const uint32_t* Ahw = st;
        const uint32_t* Alw = st + 1024;
        const uint32_t* Bhw = st + 2048;
        const uint32_t* Blw = st + 3072;

        uint32_t bh[4][2], bl[4][2];
#pragma unroll
        for (int nt = 0; nt < 4; nt++) {
            int nb = warpN * 4 + nt;
            uint2 th = *(const uint2*)(Bhw + nb * 64 + lane * 2);
            uint2 tl = *(const uint2*)(Blw + nb * 64 + lane * 2);
            bh[nt][0] = th.x; bh[nt][1] = th.y;
            bl[nt][0] = tl.x; bl[nt][1] = tl.y;
        }
#pragma unroll
        for (int mt = 0; mt < 4; mt++) {
            int rb = warpM * 4 + mt;
            uint4 ah = *(const uint4*)(Ahw + rb * 128 + lane * 4);
            uint4 al = *(const uint4*)(Alw + rb * 128 + lane * 4);
#pragma unroll
            for (int nt = 0; nt < 4; nt++) {
                mma_bf16(acc[mt][nt], ah.x, ah.y, ah.z, ah.w, bh[nt][0], bh[nt][1]);
                mma_bf16(acc[mt][nt], ah.x, ah.y, ah.z, ah.w, bl[nt][0], bl[nt][1]);
                mma_bf16(acc[mt][nt], al.x, al.y, al.z, al.w, bh[nt][0], bh[nt][1]);
            }
        }
    }
    __syncthreads();   // all compute done before sOut aliases pipeline smem

    // ---------------- fused GRU epilogue ----------------
    float* sOut = (float*)smu;  // [128][36]
    const int g = lane >> 2;
    const int tI = lane & 3;
    const int odd = tI & 1;
    const int fl = warpN * 8 + (tI >> 1);

#pragma unroll
    for (int mt = 0; mt < 4; mt++) {
#pragma unroll
        for (int nt = 0; nt < 4; nt++) {
            float c0 = acc[mt][nt][0], c1 = acc[mt][nt][1];
            float c2 = acc[mt][nt][2], c3 = acc[mt][nt][3];
            float x0 = __shfl_xor_sync(0xffffffffu, c0, 1);
            float x1 = __shfl_xor_sync(0xffffffffu, c1, 1);
            float x2 = __shfl_xor_sync(0xffffffffu, c2, 1);
            float x3 = __shfl_xor_sync(0xffffffffu, c3, 1);
            float Sr = odd ? x2 : c0;
            float Sz = odd ? x3 : c1;
            float Sn = odd ? c2 : x0;
            float hn = odd ? c3 : x1;
            int rowl = warpM * 64 + mt * 16 + g + (odd ? 8 : 0);
            int f = fl + nt * 2;
            int grow = row0 + rowl;
            float hprev = (grow < N_NODESC) ? hin[(size_t)grow * HC + ys * 32 + f] : 0.f;
            float rr = sigf(Sr + sbias[0][f]);
            float zz = sigf(Sz + sbias[1][f]);
            float nn = tanhfast(Sn - hn + sbias[2][f] + rr * (hn + sbias[3][f]));
            sOut[rowl * 36 + f] = (1.f - zz) * nn + zz * hprev;
        }
    }
    __syncthreads();
#pragma unroll
    for (int rep = 0; rep < 4; rep++) {
        int idx = tid + rep * 256;
        int row = idx >> 3, q = idx & 7;
        int grow = row0 + row;
        if (grow < N_NODESC) {
            float4 o = *(const float4*)(sOut + row * 36 + q * 4);
            *(float4*)(hout + (size_t)grow * HC + ys * 32 + q * 4) = o;
            if (write_img) {
                int f0 = ys * 32 + q * 4;
                int kt_h = f0 >> 4;
                int p0 = (q & 3) * 2;
                size_t base = ((size_t)tile * 8 + kt_h) * 1024;
                store_split4(HhiOut, HloOut, base, row, p0, o);
            }
        }
    }
}

// ---------------- pooling ----------------
__global__ void k_pool(const float* __restrict__ h, const void* __restrict__ batch) {
    int w = (blockIdx.x * blockDim.x + threadIdx.x) >> 5;
    int lane = threadIdx.x & 31;
    if (w >= N_NODESC) return;
    int g = load_idx(batch, w, g_is64);
    float4 v = *((const float4*)(h + (size_t)w * HC) + lane);
    float* p = (float*)((float4*)(g_sums + (size_t)g * HC) + lane);
    red4(p, v);
    if (lane == 0) atomicAdd(&g_cnt[g], 1.0f);
}

__global__ void k_out(const float* __restrict__ Wp, const float* __restrict__ bp,
                      float* __restrict__ out) {
    int g = blockIdx.x;
    int t = threadIdx.x;  // 128
    float c = fmaxf(g_cnt[g], 1.0f);
    float pooled = g_sums[g * HC + t] / c;
    float v = fmaxf(pooled, 0.f) * Wp[t];
    __shared__ float red[4];
#pragma unroll
    for (int o = 16; o > 0; o >>= 1) v += __shfl_down_sync(0xffffffff, v, o);
    if ((t & 31) == 0) red[t >> 5] = v;
    __syncthreads();
    if (t == 0) out[g] = red[0] + red[1] + red[2] + red[3] + bp[0];
}

// ---------------- launch ----------------
extern "C" void kernel_launch(void* const* d_in, const int* in_sizes, int n_in,
                              void* d_out, int out_size) {
    const float* x    = (const float*)d_in[0];
    const void*  ei   = d_in[1];
    const void*  batch= d_in[2];
    const float* W_in = (const float*)d_in[3];
    const float* W_mp = (const float*)d_in[4];
    const float* W_ih = (const float*)d_in[5];
    const float* W_hh = (const float*)d_in[6];
    const float* b_ih = (const float*)d_in[7];
    const float* b_hh = (const float*)d_in[8];
    const float* W_p  = (const float*)d_in[9];
    const float* b_p  = (const float*)d_in[10];
    float* out = (float*)d_out;

    void *hA, *hB, *sumsPtr, *cntPtr, *degPtr, *curPtr;
    void *bHiP, *bLoP, *hHiP, *hLoP;
    cudaGetSymbolAddress(&hA, g_hA);
    cudaGetSymbolAddress(&hB, g_hB);
    cudaGetSymbolAddress(&sumsPtr, g_sums);
    cudaGetSymbolAddress(&cntPtr, g_cnt);
    cudaGetSymbolAddress(&degPtr, g_deg);
    cudaGetSymbolAddress(&curPtr, g_cursor);
    cudaGetSymbolAddress(&bHiP, g_BHi);
    cudaGetSymbolAddress(&bLoP, g_BLo);
    cudaGetSymbolAddress(&hHiP, g_HHi);
    cudaGetSymbolAddress(&hLoP, g_HLo);
    const uint32_t* BHi = (const uint32_t*)bHiP;
    const uint32_t* BLo = (const uint32_t*)bLoP;
    uint32_t* HHi = (uint32_t*)hHiP;  // [2][AIMG_WORDS]
    uint32_t* HLo = (uint32_t*)hLoP;

    cudaFuncSetAttribute(k_gemm, cudaFuncAttributeMaxDynamicSharedMemorySize, SMEM_DYN);

    k_detect<<<1, 256>>>((const int*)ei);

    // CSR build
    cudaMemsetAsync(degPtr, 0, N_NODESC * sizeof(int), 0);
    cudaMemsetAsync(curPtr, 0, N_NODESC * sizeof(int), 0);
    k_deg<<<(N_EDGESC + 255) / 256, 256>>>(ei);
    k_scan1<<<NSCANB, 256>>>();
    k_scan2<<<1, 32>>>();
    k_scan3<<<NSCANB, 256>>>();
    k_fill<<<(N_EDGESC + 255) / 256, 256>>>(ei);

    // weights
    k_prep_wc<<<(STEPSC * H3C * HC + 255) / 256, 256>>>(W_mp, W_ih);
    k_prep_bimg<<<(STEPSC * BIMG_STEP_W + 255) / 256, 256>>>(W_hh);

    k_input<<<(N_NODESC + 63) / 64, 128>>>(x, W_in, (float*)hA);
    k_h2img<<<(int)(((long long)N_NODESC * 32 + 255) / 256), 256>>>(
        (const float*)hA, HHi, HLo);

    float* hcur = (float*)hA;
    float* hnext = (float*)hB;
    for (int s = 0; s < STEPSC; s++) {
        int pin = s & 1, pout = (s + 1) & 1;
        k_gather<<<(int)(((long long)N_NODESC * 32 + 255) / 256), 256>>>(hcur);
        dim3 grid(NTILES, 4);
        k_gemm<<<grid, 256, SMEM_DYN>>>(
            hcur, hnext,
            BHi + (size_t)s * BIMG_STEP_W, BLo + (size_t)s * BIMG_STEP_W,
            HHi + (size_t)pin * AIMG_WORDS, HLo + (size_t)pin * AIMG_WORDS,
            HHi + (size_t)pout * AIMG_WORDS, HLo + (size_t)pout * AIMG_WORDS,
            b_ih, b_hh, (s < STEPSC - 1) ? 1 : 0);
        float* tmp = hcur; hcur = hnext; hnext = tmp;
    }
    cudaMemsetAsync(sumsPtr, 0, (size_t)N_GRAPHSC * HC * sizeof(float), 0);
    cudaMemsetAsync(cntPtr, 0, (size_t)N_GRAPHSC * sizeof(float), 0);
    k_pool<<<(int)(((long long)N_NODESC * 32 + 255) / 256), 256>>>(hcur, batch);
    k_out<<<N_GRAPHSC, 128>>>(W_p, b_p, out);
}